// round 13
// baseline (speedup 1.0000x reference)
#include <cuda_runtime.h>
#include <cstdint>
#include <cfloat>
#include <math.h>

#define VOC   10000
#define EMB   512
#define HID   1024
#define BATCH 128
#define SEQT  64
#define STEPS 63
#define CTXW  4096
#define G4H   4096
#define NBLK  128
#define NTHR  256
#define NTILE 313
#define LDW1  (EMB + CTXW)   // 4608

// ---- static smem layout: double-buffered K=16 chunk tiles, stride 48 B ----
#define KCH   16
#define ASTRB 48
#define ATERM 6144            // 128 rows * 48
#define ABUF  18432           // 3 terms
#define WTERM 1536            // 32 rows * 48
#define OW_   18432           // W region within a buffer
#define BUFSZ 23040           // ABUF + 3*WTERM
#define OTILE 46080
#define OTOK  46084
#define OSC   46088
#define ORV   46208           // float[256]
#define ORI   47232           // int[256]
#define SMSZ  48256

typedef unsigned short ush;

// ---------------- persistent device scratch ----------------------------------
__device__ __align__(128) float g_hn[BATCH * G4H];
__device__ __align__(128) float g_pmax[BATCH][NTILE];
__device__ __align__(128) int   g_pidx[BATCH][NTILE];
__device__ int g_ctrC[STEPS];
__device__ unsigned g_count;
__device__ unsigned g_gen;

// pre-converted bf16 3-term storage (term 0=hi, 1=mid, 2=lo)
__device__ __align__(128) ush gbW1 [3][4096 * LDW1];
__device__ __align__(128) ush gbWh1[3][4096 * HID];
__device__ __align__(128) ush gbW2 [3][4096 * HID];
__device__ __align__(128) ush gbWh2[3][4096 * HID];
__device__ __align__(128) ush gbWo [3][VOC * HID];
__device__ __align__(128) ush gbHn [3][BATCH * CTXW];
__device__ __align__(128) ush gbX  [3][BATCH * EMB];
__device__ __align__(128) ush gbH1 [2][3][BATCH * HID];
__device__ __align__(128) ush gbH2 [2][3][BATCH * HID];

__device__ __forceinline__ float sigmf(float x) { return 1.0f / (1.0f + expf(-x)); }

__device__ __forceinline__ uint32_t smem_u32(const void* p) {
    uint32_t a;
    asm("{ .reg .u64 t; cvta.to.shared.u64 t, %1; cvt.u32.u64 %0, t; }" : "=r"(a) : "l"(p));
    return a;
}

__device__ __forceinline__ void cvt3(float x, ush& a, ush& b, ush& c) {
    float f;
    asm("cvt.rn.bf16.f32 %0, %1;" : "=h"(a) : "f"(x));
    asm("cvt.f32.bf16 %0, %1;" : "=f"(f) : "h"(a));
    float r = x - f;
    asm("cvt.rn.bf16.f32 %0, %1;" : "=h"(b) : "f"(r));
    asm("cvt.f32.bf16 %0, %1;" : "=f"(f) : "h"(b));
    asm("cvt.rn.bf16.f32 %0, %1;" : "=h"(c) : "f"(r - f));
}

// grid-strided fp32 -> 3xbf16 conversion, 8 elems per iteration
__device__ void conv_arr(ush* d0, ush* d1, ush* d2,
                         const float* __restrict__ s, int n8) {
    const int stride = NBLK * NTHR;
    for (int i = blockIdx.x * NTHR + threadIdx.x; i < n8; i += stride) {
        const float4* p = (const float4*)(s + (size_t)i * 8);
        float4 v0 = __ldcg(p), v1 = __ldcg(p + 1);
        float xs[8] = {v0.x, v0.y, v0.z, v0.w, v1.x, v1.y, v1.z, v1.w};
        ush t0[8], t1[8], t2[8];
        #pragma unroll
        for (int e = 0; e < 8; e++) cvt3(xs[e], t0[e], t1[e], t2[e]);
        uint4 u;
        u.x = t0[0] | ((uint32_t)t0[1] << 16); u.y = t0[2] | ((uint32_t)t0[3] << 16);
        u.z = t0[4] | ((uint32_t)t0[5] << 16); u.w = t0[6] | ((uint32_t)t0[7] << 16);
        *(uint4*)(d0 + (size_t)i * 8) = u;
        u.x = t1[0] | ((uint32_t)t1[1] << 16); u.y = t1[2] | ((uint32_t)t1[3] << 16);
        u.z = t1[4] | ((uint32_t)t1[5] << 16); u.w = t1[6] | ((uint32_t)t1[7] << 16);
        *(uint4*)(d1 + (size_t)i * 8) = u;
        u.x = t2[0] | ((uint32_t)t2[1] << 16); u.y = t2[2] | ((uint32_t)t2[3] << 16);
        u.z = t2[4] | ((uint32_t)t2[5] << 16); u.w = t2[6] | ((uint32_t)t2[7] << 16);
        *(uint4*)(d2 + (size_t)i * 8) = u;
    }
}

// ---------------- grid-wide sense barrier ------------------------------------
__device__ __forceinline__ void gbar() {
    __syncthreads();
    if (threadIdx.x == 0) {
        __threadfence();
        unsigned gen = *((volatile unsigned*)&g_gen);
        unsigned arrived = atomicAdd(&g_count, 1);
        if (arrived == NBLK - 1) {
            atomicExch(&g_count, 0);
            __threadfence();
            atomicAdd(&g_gen, 1);
        } else {
            while (*((volatile unsigned*)&g_gen) == gen) __nanosleep(64);
        }
        __threadfence();
    }
    __syncthreads();
}

// ---------------- warp-MMA primitives (base sm_80 PTX) ------------------------
__device__ __forceinline__ void ldsm4(uint32_t (&r)[4], uint32_t addr) {
    asm volatile("ldmatrix.sync.aligned.m8n8.x4.shared.b16 {%0,%1,%2,%3}, [%4];"
        : "=r"(r[0]), "=r"(r[1]), "=r"(r[2]), "=r"(r[3]) : "r"(addr));
}
__device__ __forceinline__ void mma_bf16(float (&c)[4], const uint32_t (&a)[4],
                                         uint32_t b0, uint32_t b1) {
    asm volatile("mma.sync.aligned.m16n8k16.row.col.f32.bf16.bf16.f32 "
        "{%0,%1,%2,%3}, {%4,%5,%6,%7}, {%8,%9}, {%0,%1,%2,%3};"
        : "+f"(c[0]), "+f"(c[1]), "+f"(c[2]), "+f"(c[3])
        : "r"(a[0]), "r"(a[1]), "r"(a[2]), "r"(a[3]), "r"(b0), "r"(b1));
}

// ---------------- GEMM: C[128x32] += A[128xK] * Wsel^T ------------------------
// K=16 chunks, DOUBLE-BUFFERED smem: MMA on buf[c] overlaps STS of buf[c+1]
// and LDG prefetch of chunk c+2. One __syncthreads per chunk.
template<bool GATED>
__device__ __forceinline__ void run_gemm(float (&acc)[2][2][4],
    const ush* __restrict__ A0, const ush* __restrict__ A1,
    const ush* __restrict__ A2, int lda,
    const ush* __restrict__ W0, const ush* __restrict__ W1,
    const ush* __restrict__ W2, int ldw, int wcol0,
    int rowsel, int rowclamp, int K,
    char* SM, uint32_t smb, int tid)
{
    const int lane = tid & 31, wid = tid >> 5;
    const int rg = wid >> 1, cgp = wid & 1;
    const int sub = lane >> 3, rin = lane & 7;
    const int rA = rg * 32 + ((sub & 1) << 3) + rin;
    const int cA = (sub >> 1) << 3;
    const int rW = cgp * 16 + ((sub >> 1) << 3) + rin;
    const int cW = (sub & 1) << 3;
    const uint32_t aB = smb + rA * ASTRB + cA * 2;
    const uint32_t wB = smb + OW_ + rW * ASTRB + cW * 2;

    // A staging: 3 iterations, term=it, row=tid&127, half=tid>>7 (conflict-free)
    const ush* aptr[3]; int asoff[3];
    const int arow = tid & 127, ahalf = tid >> 7;
    #pragma unroll
    for (int it = 0; it < 3; it++) {
        const ush* Ap = (it == 0) ? A0 : ((it == 1) ? A1 : A2);
        aptr[it] = Ap + (size_t)arow * lda + ahalf * 8;
        asoff[it] = it * ATERM + arow * ASTRB + ahalf * 16;
    }
    // W staging: tid<192, term=tid>>6, row=(tid&63)&31, half=(tid&63)>>5
    const bool wv = (tid < 192);
    const int wterm = (tid >> 6) & 3;
    const int wrow = tid & 31, whalf = (tid >> 5) & 1;
    int grow;
    if (GATED) grow = (wrow >> 3) * HID + rowsel + (wrow & 7);
    else { grow = rowsel + wrow; if (grow > rowclamp) grow = rowclamp; }
    const ush* Wp = (wterm == 0) ? W0 : ((wterm == 1) ? W1 : W2);
    const ush* wptr = Wp + (size_t)grow * ldw + wcol0 + whalf * 8;
    const int wsoff = OW_ + wterm * WTERM + wrow * ASTRB + whalf * 16;

    const int nch = K / KCH;
    uint4 pa[3], pw;
    #pragma unroll
    for (int it = 0; it < 3; it++) pa[it] = __ldcg((const uint4*)aptr[it]);
    if (wv) pw = __ldg((const uint4*)wptr);

    __syncthreads();   // prior smem users done before first STS
    #pragma unroll
    for (int it = 0; it < 3; it++) *(uint4*)(SM + asoff[it]) = pa[it];
    if (wv) *(uint4*)(SM + wsoff) = pw;
    if (nch > 1) {
        #pragma unroll
        for (int it = 0; it < 3; it++)
            pa[it] = __ldcg((const uint4*)(aptr[it] + KCH));
        if (wv) pw = __ldg((const uint4*)(wptr + KCH));
    }
    __syncthreads();

    for (int c = 0; c < nch; c++) {
        const int bo = (c & 1) * BUFSZ;
        uint32_t a[2][3][4], w[3][4];
        #pragma unroll
        for (int h = 0; h < 2; h++)
            #pragma unroll
            for (int tt = 0; tt < 3; tt++)
                ldsm4(a[h][tt], aB + bo + tt * ATERM + h * 16 * ASTRB);
        #pragma unroll
        for (int tt = 0; tt < 3; tt++)
            ldsm4(w[tt], wB + bo + tt * WTERM);
        if (c + 1 < nch) {
            const int bo2 = ((c + 1) & 1) * BUFSZ;
            #pragma unroll
            for (int it = 0; it < 3; it++) *(uint4*)(SM + bo2 + asoff[it]) = pa[it];
            if (wv) *(uint4*)(SM + bo2 + wsoff) = pw;
            if (c + 2 < nch) {
                const int off = (c + 2) * KCH;
                #pragma unroll
                for (int it = 0; it < 3; it++)
                    pa[it] = __ldcg((const uint4*)(aptr[it] + off));
                if (wv) pw = __ldg((const uint4*)(wptr + off));
            }
        }
        const int PA[6] = {0, 0, 1, 1, 0, 2};
        const int PW[6] = {0, 1, 0, 1, 2, 0};
        #pragma unroll
        for (int p = 0; p < 6; p++)
            #pragma unroll
            for (int h = 0; h < 2; h++)
                #pragma unroll
                for (int f = 0; f < 2; f++)
                    mma_bf16(acc[h][f], a[h][PA[p]], w[PW[p]][2*f], w[PW[p]][2*f+1]);
        __syncthreads();
    }
}

__global__ void __launch_bounds__(NTHR, 1) lstm_kernel(
    const float* __restrict__ h_n,   const int* __restrict__ expanded,
    const int* __restrict__ tfmask,  const float* __restrict__ dropm,
    const float* __restrict__ embW,
    const float* __restrict__ Wih1,  const float* __restrict__ Whh1,
    const float* __restrict__ bih1,  const float* __restrict__ bhh1,
    const float* __restrict__ Wih2,  const float* __restrict__ Whh2,
    const float* __restrict__ bih2,  const float* __restrict__ bhh2,
    const float* __restrict__ Wout,  const float* __restrict__ bout,
    float* __restrict__ out)
{
    __shared__ __align__(1024) char SM[SMSZ];
    const int tid = threadIdx.x;
    const int blk = blockIdx.x;
    const int j0  = blk * 8;
    const int lane = tid & 31, wid = tid >> 5;
    const int rg = wid >> 1, cgp = wid & 1;
    const int gid = lane >> 2, tig = lane & 3;
    const uint32_t smb = smem_u32(SM);

    // ---------------- init: zero states, x0, pre-convert everything ----------
    for (int i = blk * NTHR + tid; i < 3 * BATCH * HID; i += NBLK * NTHR) {
        int term = i / (BATCH * HID), o = i % (BATCH * HID);
        gbH1[0][term][o] = 0; gbH2[0][term][o] = 0;
    }
    for (int i = blk * NTHR + tid; i < BATCH * EMB; i += NBLK * NTHR) {
        int b = i / EMB; int e = i - b * EMB;
        int tok = expanded[b * SEQT];
        float x = dropm[tok] * embW[(size_t)tok * EMB + e];
        ush a, bb, c; cvt3(x, a, bb, c);
        gbX[0][i] = a; gbX[1][i] = bb; gbX[2][i] = c;
    }
    if (blk == 0)
        for (int i = tid; i < STEPS; i += NTHR) g_ctrC[i] = 0;

    conv_arr(gbW1[0],  gbW1[1],  gbW1[2],  Wih1, 4096 * LDW1 / 8);
    conv_arr(gbWh1[0], gbWh1[1], gbWh1[2], Whh1, 4096 * HID / 8);
    conv_arr(gbW2[0],  gbW2[1],  gbW2[2],  Wih2, 4096 * HID / 8);
    conv_arr(gbWh2[0], gbWh2[1], gbWh2[2], Whh2, 4096 * HID / 8);
    conv_arr(gbWo[0],  gbWo[1],  gbWo[2],  Wout, VOC * HID / 8);
    conv_arr(gbHn[0],  gbHn[1],  gbHn[2],  h_n,  BATCH * CTXW / 8);
    gbar();

    // one-time: g_hn = h_n @ Wih1[:, E:].T + bih1 + bhh1 (this block's gate tile)
    {
        float acc[2][2][4];
        #pragma unroll
        for (int h = 0; h < 2; h++)
            #pragma unroll
            for (int f = 0; f < 2; f++)
                #pragma unroll
                for (int q = 0; q < 4; q++) acc[h][f][q] = 0.f;
        run_gemm<true>(acc, gbHn[0], gbHn[1], gbHn[2], CTXW,
                       gbW1[0], gbW1[1], gbW1[2], LDW1, EMB, j0, 0, CTXW,
                       SM, smb, tid);
        #pragma unroll
        for (int h = 0; h < 2; h++) {
            int rAr = rg * 32 + h * 16 + gid;
            #pragma unroll
            for (int f = 0; f < 2; f++) {
                int tc = cgp * 16 + f * 8 + 2 * tig;
                int col = ((tc >> 3) * HID) + j0 + (tc & 7);
                float b0 = __ldg(bih1 + col) + __ldg(bhh1 + col);
                float b1 = __ldg(bih1 + col + 1) + __ldg(bhh1 + col + 1);
                *(float2*)&g_hn[(size_t)rAr * G4H + col] =
                    make_float2(acc[h][f][0] + b0, acc[h][f][1] + b1);
                *(float2*)&g_hn[(size_t)(rAr + 8) * G4H + col] =
                    make_float2(acc[h][f][2] + b0, acc[h][f][3] + b1);
            }
        }
    }
    gbar();

    float c1s[4] = {0.f, 0.f, 0.f, 0.f};
    float c2s[4] = {0.f, 0.f, 0.f, 0.f};
    float* sGf = (float*)SM;   // aliased gate tile [128][34]

    for (int t = 0; t < STEPS; t++) {
        const int ob_ = t & 1, nb_ = (t + 1) & 1;

        // ---------- phase A: layer-1 gates + cell ----------
        {
            float acc[2][2][4];
            #pragma unroll
            for (int h = 0; h < 2; h++) {
                int rAr = rg * 32 + h * 16 + gid;
                #pragma unroll
                for (int f = 0; f < 2; f++) {
                    int tc = cgp * 16 + f * 8 + 2 * tig;
                    int col = ((tc >> 3) * HID) + j0 + (tc & 7);
                    float2 u = *(const float2*)&g_hn[(size_t)rAr * G4H + col];
                    float2 v = *(const float2*)&g_hn[(size_t)(rAr + 8) * G4H + col];
                    acc[h][f][0] = u.x; acc[h][f][1] = u.y;
                    acc[h][f][2] = v.x; acc[h][f][3] = v.y;
                }
            }
            run_gemm<true>(acc, gbX[0], gbX[1], gbX[2], EMB,
                           gbW1[0], gbW1[1], gbW1[2], LDW1, 0, j0, 0, EMB,
                           SM, smb, tid);
            run_gemm<true>(acc, gbH1[ob_][0], gbH1[ob_][1], gbH1[ob_][2], HID,
                           gbWh1[0], gbWh1[1], gbWh1[2], HID, 0, j0, 0, HID,
                           SM, smb, tid);
            #pragma unroll
            for (int h = 0; h < 2; h++) {
                int rAr = rg * 32 + h * 16 + gid;
                #pragma unroll
                for (int f = 0; f < 2; f++) {
                    int tc = cgp * 16 + f * 8 + 2 * tig;
                    *(float2*)&sGf[rAr * 34 + tc] = make_float2(acc[h][f][0], acc[h][f][1]);
                    *(float2*)&sGf[(rAr + 8) * 34 + tc] = make_float2(acc[h][f][2], acc[h][f][3]);
                }
            }
            __syncthreads();
            #pragma unroll
            for (int jj = 0; jj < 4; jj++) {
                int p = tid + jj * NTHR;
                int r = p >> 3, jl = p & 7;
                float iv = sGf[r * 34 + jl];
                float fv = sGf[r * 34 + 8 + jl];
                float gv = sGf[r * 34 + 16 + jl];
                float ov = sGf[r * 34 + 24 + jl];
                float cn = sigmf(fv) * c1s[jj] + sigmf(iv) * tanhf(gv);
                c1s[jj] = cn;
                float hv = sigmf(ov) * tanhf(cn);
                ush a, bb, c; cvt3(hv, a, bb, c);
                int o = r * HID + j0 + jl;
                gbH1[nb_][0][o] = a; gbH1[nb_][1][o] = bb; gbH1[nb_][2][o] = c;
            }
        }
        gbar();

        // ---------- phase B: layer-2 gates + cell ----------
        {
            float acc[2][2][4];
            #pragma unroll
            for (int f = 0; f < 2; f++) {
                int tc = cgp * 16 + f * 8 + 2 * tig;
                int col = ((tc >> 3) * HID) + j0 + (tc & 7);
                float b0 = __ldg(bih2 + col) + __ldg(bhh2 + col);
                float b1 = __ldg(bih2 + col + 1) + __ldg(bhh2 + col + 1);
                #pragma unroll
                for (int h = 0; h < 2; h++) {
                    acc[h][f][0] = b0; acc[h][f][1] = b1;
                    acc[h][f][2] = b0; acc[h][f][3] = b1;
                }
            }
            run_gemm<true>(acc, gbH1[nb_][0], gbH1[nb_][1], gbH1[nb_][2], HID,
                           gbW2[0], gbW2[1], gbW2[2], HID, 0, j0, 0, HID,
                           SM, smb, tid);
            run_gemm<true>(acc, gbH2[ob_][0], gbH2[ob_][1], gbH2[ob_][2], HID,
                           gbWh2[0], gbWh2[1], gbWh2[2], HID, 0, j0, 0, HID,
                           SM, smb, tid);
            #pragma unroll
            for (int h = 0; h < 2; h++) {
                int rAr = rg * 32 + h * 16 + gid;
                #pragma unroll
                for (int f = 0; f < 2; f++) {
                    int tc = cgp * 16 + f * 8 + 2 * tig;
                    *(float2*)&sGf[rAr * 34 + tc] = make_float2(acc[h][f][0], acc[h][f][1]);
                    *(float2*)&sGf[(rAr + 8) * 34 + tc] = make_float2(acc[h][f][2], acc[h][f][3]);
                }
            }
            __syncthreads();
            #pragma unroll
            for (int jj = 0; jj < 4; jj++) {
                int p = tid + jj * NTHR;
                int r = p >> 3, jl = p & 7;
                float iv = sGf[r * 34 + jl];
                float fv = sGf[r * 34 + 8 + jl];
                float gv = sGf[r * 34 + 16 + jl];
                float ov = sGf[r * 34 + 24 + jl];
                float cn = sigmf(fv) * c2s[jj] + sigmf(iv) * tanhf(gv);
                c2s[jj] = cn;
                float hv = sigmf(ov) * tanhf(cn);
                ush a, bb, c; cvt3(hv, a, bb, c);
                int o = r * HID + j0 + jl;
                gbH2[nb_][0][o] = a; gbH2[nb_][1][o] = bb; gbH2[nb_][2][o] = c;
            }
        }
        gbar();

        // ---------- phase C: logits tiles (work stealing) ----------
        for (;;) {
            __syncthreads();
            if (tid == 0) *(int*)(SM + OTILE) = atomicAdd(&g_ctrC[t], 1);
            __syncthreads();
            int tile = *(int*)(SM + OTILE);
            if (tile >= NTILE) break;
            int n0 = tile * 32;
            float acc[2][2][4];
            #pragma unroll
            for (int h = 0; h < 2; h++)
                #pragma unroll
                for (int f = 0; f < 2; f++)
                    #pragma unroll
                    for (int q = 0; q < 4; q++) acc[h][f][q] = 0.f;
            run_gemm<false>(acc, gbH2[nb_][0], gbH2[nb_][1], gbH2[nb_][2], HID,
                            gbWo[0], gbWo[1], gbWo[2], HID, 0, n0, VOC - 1, HID,
                            SM, smb, tid);
            float* sMxV = (float*)SM;
            int*   sMxI = (int*)(SM + 1024);
            #pragma unroll
            for (int h = 0; h < 2; h++) {
                int rAr = rg * 32 + h * 16 + gid;
                float bvA = -FLT_MAX, bvB = -FLT_MAX;
                int   bcA = 0x7fffffff, bcB = 0x7fffffff;
                #pragma unroll
                for (int f = 0; f < 2; f++) {
                    int col0 = n0 + cgp * 16 + f * 8 + 2 * tig;
                    if (col0 < VOC) {
                        float b0 = __ldg(bout + col0);
                        float b1 = __ldg(bout + col0 + 1);
                        float vA0 = acc[h][f][0] + b0, vA1 = acc[h][f][1] + b1;
                        float vB0 = acc[h][f][2] + b0, vB1 = acc[h][f][3] + b1;
                        *(float2*)&out[((size_t)t * BATCH + rAr) * VOC + col0] =
                            make_float2(vA0, vA1);
                        *(float2*)&out[((size_t)t * BATCH + rAr + 8) * VOC + col0] =
                            make_float2(vB0, vB1);
                        if (vA0 > bvA) { bvA = vA0; bcA = col0; }
                        if (vA1 > bvA) { bvA = vA1; bcA = col0 + 1; }
                        if (vB0 > bvB) { bvB = vB0; bcB = col0; }
                        if (vB1 > bvB) { bvB = vB1; bcB = col0 + 1; }
                    }
                }
                #pragma unroll
                for (int d = 1; d <= 2; d <<= 1) {
                    float ov = __shfl_xor_sync(0xffffffffu, bvA, d);
                    int   oc = __shfl_xor_sync(0xffffffffu, bcA, d);
                    if (ov > bvA || (ov == bvA && oc < bcA)) { bvA = ov; bcA = oc; }
                    ov = __shfl_xor_sync(0xffffffffu, bvB, d);
                    oc = __shfl_xor_sync(0xffffffffu, bcB, d);
                    if (ov > bvB || (ov == bvB && oc < bcB)) { bvB = ov; bcB = oc; }
                }
                if (tig == 0) {
                    sMxV[rAr * 2 + cgp] = bvA; sMxI[rAr * 2 + cgp] = bcA;
                    sMxV[(rAr + 8) * 2 + cgp] = bvB; sMxI[(rAr + 8) * 2 + cgp] = bcB;
                }
            }
            __syncthreads();
            if (tid < BATCH) {
                float v0 = sMxV[tid * 2], v1 = sMxV[tid * 2 + 1];
                int   i0 = sMxI[tid * 2], i1 = sMxI[tid * 2 + 1];
                if (v1 > v0 || (v1 == v0 && i1 < i0)) { v0 = v1; i0 = i1; }
                g_pmax[tid][tile] = v0;
                g_pidx[tid][tile] = i0;
            }
        }
        gbar();

        // ---------- phase D: final argmax + next input ----------
        {
            float* s_rv = (float*)(SM + ORV);
            int*   s_ri = (int*)(SM + ORI);
            int b = blk;
            float bv = -FLT_MAX; int bc = 0x7fffffff;
            for (int tile = tid; tile < NTILE; tile += NTHR) {
                float v = __ldcg(&g_pmax[b][tile]);
                int   c = __ldcg(&g_pidx[b][tile]);
                if (v > bv || (v == bv && c < bc)) { bv = v; bc = c; }
            }
            s_rv[tid] = bv; s_ri[tid] = bc;
            __syncthreads();
            for (int s = NTHR / 2; s > 0; s >>= 1) {
                if (tid < s) {
                    float v = s_rv[tid + s]; int c = s_ri[tid + s];
                    if (v > s_rv[tid] || (v == s_rv[tid] && c < s_ri[tid])) {
                        s_rv[tid] = v; s_ri[tid] = c;
                    }
                }
                __syncthreads();
            }
            if (tid == 0) {
                int m = tfmask[t * BATCH + b];
                int tok; float sc;
                if (m == 1) { tok = s_ri[0]; sc = 1.0f; }
                else        { tok = expanded[b * SEQT + t + 1]; sc = dropm[tok]; }
                *(int*)(SM + OTOK) = tok;
                *(float*)(SM + OSC) = sc;
            }
            __syncthreads();
            int tok = *(int*)(SM + OTOK);
            float sc = *(float*)(SM + OSC);
            #pragma unroll
            for (int e0 = 0; e0 < 2; e0++) {
                int e = tid + e0 * 256;
                float x = sc * embW[(size_t)tok * EMB + e];
                ush a, bb, c; cvt3(x, a, bb, c);
                int o = b * EMB + e;
                gbX[0][o] = a; gbX[1][o] = bb; gbX[2][o] = c;
            }
        }
        gbar();
    }
}

extern "C" void kernel_launch(void* const* d_in, const int* in_sizes, int n_in,
                              void* d_out, int out_size) {
    (void)in_sizes; (void)n_in; (void)out_size;
    lstm_kernel<<<NBLK, NTHR>>>(
        (const float*)d_in[0],  (const int*)d_in[1],  (const int*)d_in[2],
        (const float*)d_in[3],  (const float*)d_in[4], (const float*)d_in[5],
        (const float*)d_in[6],  (const float*)d_in[7], (const float*)d_in[8],
        (const float*)d_in[9],  (const float*)d_in[10], (const float*)d_in[11],
        (const float*)d_in[12], (const float*)d_in[13], (const float*)d_in[14],
        (float*)d_out);
}

// round 16
// speedup vs baseline: 1.9583x; 1.9583x over previous
#include <cuda_runtime.h>
#include <cstdint>
#include <cfloat>
#include <math.h>

#define VOC   10000
#define EMB   512
#define HID   1024
#define BATCH 128
#define SEQT  64
#define STEPS 63
#define CTXW  4096
#define G4H   4096
#define NBLK  128
#define NTHR  256
#define NTILE 313
#define LDW1  (EMB + CTXW)   // 4608

// ---- static smem layout (bytes); A/W tiles padded row stride 80 B ----
#define ASTR  80
#define OA0   0
#define OA1   10240          // A end 20480
#define OW0   20480          // 2 W terms x 2560 -> end 25600
#define OTILE 25600
#define OTOK  25604
#define OSC   25608
#define ORV   25728          // float[256]
#define ORI   26752          // int[256]
#define SMSZ  27776

typedef unsigned short ush;

// ---------------- persistent device scratch ----------------------------------
__device__ __align__(128) float g_hn[BATCH * G4H];
__device__ __align__(128) float g_pmax[BATCH][NTILE];
__device__ __align__(128) int   g_pidx[BATCH][NTILE];
__device__ int g_ctrC[STEPS];
__device__ unsigned g_count;
__device__ unsigned g_gen;

// pre-converted bf16 2-term storage (term 0=hi, 1=mid)
__device__ __align__(128) ush gbW1 [2][4096 * LDW1];
__device__ __align__(128) ush gbWh1[2][4096 * HID];
__device__ __align__(128) ush gbW2 [2][4096 * HID];
__device__ __align__(128) ush gbWh2[2][4096 * HID];
__device__ __align__(128) ush gbWo [2][VOC * HID];
__device__ __align__(128) ush gbHn [2][BATCH * CTXW];
__device__ __align__(128) ush gbX  [2][BATCH * EMB];
__device__ __align__(128) ush gbH1 [2][2][BATCH * HID];
__device__ __align__(128) ush gbH2 [2][2][BATCH * HID];

__device__ __forceinline__ float sigmf(float x) { return 1.0f / (1.0f + expf(-x)); }

__device__ __forceinline__ uint32_t smem_u32(const void* p) {
    uint32_t a;
    asm("{ .reg .u64 t; cvta.to.shared.u64 t, %1; cvt.u32.u64 %0, t; }" : "=r"(a) : "l"(p));
    return a;
}

__device__ __forceinline__ void cvt2(float x, ush& a, ush& b) {
    float f;
    asm("cvt.rn.bf16.f32 %0, %1;" : "=h"(a) : "f"(x));
    asm("cvt.f32.bf16 %0, %1;" : "=f"(f) : "h"(a));
    asm("cvt.rn.bf16.f32 %0, %1;" : "=h"(b) : "f"(x - f));
}

// grid-strided fp32 -> 2xbf16 conversion, 8 elems per iteration
__device__ void conv_arr(ush* d0, ush* d1, const float* __restrict__ s, int n8) {
    const int stride = NBLK * NTHR;
    for (int i = blockIdx.x * NTHR + threadIdx.x; i < n8; i += stride) {
        const float4* p = (const float4*)(s + (size_t)i * 8);
        float4 v0 = __ldcg(p), v1 = __ldcg(p + 1);
        float xs[8] = {v0.x, v0.y, v0.z, v0.w, v1.x, v1.y, v1.z, v1.w};
        ush t0[8], t1[8];
        #pragma unroll
        for (int e = 0; e < 8; e++) cvt2(xs[e], t0[e], t1[e]);
        uint4 u;
        u.x = t0[0] | ((uint32_t)t0[1] << 16); u.y = t0[2] | ((uint32_t)t0[3] << 16);
        u.z = t0[4] | ((uint32_t)t0[5] << 16); u.w = t0[6] | ((uint32_t)t0[7] << 16);
        *(uint4*)(d0 + (size_t)i * 8) = u;
        u.x = t1[0] | ((uint32_t)t1[1] << 16); u.y = t1[2] | ((uint32_t)t1[3] << 16);
        u.z = t1[4] | ((uint32_t)t1[5] << 16); u.w = t1[6] | ((uint32_t)t1[7] << 16);
        *(uint4*)(d1 + (size_t)i * 8) = u;
    }
}

// ---------------- grid-wide sense barrier ------------------------------------
__device__ __forceinline__ void gbar() {
    __syncthreads();
    if (threadIdx.x == 0) {
        __threadfence();
        unsigned gen = *((volatile unsigned*)&g_gen);
        unsigned arrived = atomicAdd(&g_count, 1);
        if (arrived == NBLK - 1) {
            atomicExch(&g_count, 0);
            __threadfence();
            atomicAdd(&g_gen, 1);
        } else {
            while (*((volatile unsigned*)&g_gen) == gen) __nanosleep(64);
        }
        __threadfence();
    }
    __syncthreads();
}

// ---------------- warp-MMA primitives (base sm_80 PTX) ------------------------
__device__ __forceinline__ void ldsm4(uint32_t (&r)[4], uint32_t addr) {
    asm volatile("ldmatrix.sync.aligned.m8n8.x4.shared.b16 {%0,%1,%2,%3}, [%4];"
        : "=r"(r[0]), "=r"(r[1]), "=r"(r[2]), "=r"(r[3]) : "r"(addr));
}
__device__ __forceinline__ void mma_bf16(float (&c)[4], const uint32_t (&a)[4],
                                         uint32_t b0, uint32_t b1) {
    asm volatile("mma.sync.aligned.m16n8k16.row.col.f32.bf16.bf16.f32 "
        "{%0,%1,%2,%3}, {%4,%5,%6,%7}, {%8,%9}, {%0,%1,%2,%3};"
        : "+f"(c[0]), "+f"(c[1]), "+f"(c[2]), "+f"(c[3])
        : "r"(a[0]), "r"(a[1]), "r"(a[2]), "r"(a[3]), "r"(b0), "r"(b1));
}

// ---------------- GEMM: C[128x32] += A[128xK] * Wsel^T ------------------------
// 2-term bf16 split, 4 mma passes {00,01,10,11} per k16 slice; 2 slices per
// K=32 chunk (ks loop — this was missing in R15 and halved K). Staging
// register-prefetched one chunk ahead (R12 scheme).
template<bool GATED>
__device__ __forceinline__ void run_gemm(float (&acc)[2][2][4],
    const ush* __restrict__ A0, const ush* __restrict__ A1, int lda,
    const ush* __restrict__ W0, const ush* __restrict__ W1, int ldw, int wcol0,
    int rowsel, int rowclamp, int K,
    char* SM, uint32_t smb, int tid)
{
    const int lane = tid & 31, wid = tid >> 5;
    const int rg = wid >> 1, cgp = wid & 1;
    const int sub = lane >> 3, rin = lane & 7;
    const int rA = rg * 32 + ((sub & 1) << 3) + rin;
    const int cA = (sub >> 1) << 3;
    const int rW = cgp * 16 + ((sub >> 1) << 3) + rin;
    const int cW = (sub & 1) << 3;
    const uint32_t aB = smb + rA * ASTR + cA * 2;
    const uint32_t wB = smb + OW0 + rW * ASTR + cW * 2;

    // A staging: 4 iterations of 256 -> 2 terms x 128 rows x 4 uint4
    const ush* aptr[4]; int asoff[4];
    #pragma unroll
    for (int it = 0; it < 4; it++) {
        int idx = tid + it * 256;
        int term = idx >> 9, rem = idx & 511;
        int row = rem >> 2, q = rem & 3;
        const ush* Ap = term ? A1 : A0;
        aptr[it] = Ap + (size_t)row * lda + q * 8;
        asoff[it] = term * 10240 + row * ASTR + q * 16;
    }
    // W staging: 1 slot/thread: term=tid>>7, row=(tid&127)>>2, quad=tid&3
    const int wterm = tid >> 7;
    const int wrow = (tid & 127) >> 2, wq = tid & 3;
    int grow;
    if (GATED) grow = (wrow >> 3) * HID + rowsel + (wrow & 7);
    else { grow = rowsel + wrow; if (grow > rowclamp) grow = rowclamp; }
    const ush* Wp = wterm ? W1 : W0;
    const ush* wptr = Wp + (size_t)grow * ldw + wcol0 + wq * 8;
    const int wsoff = OW0 + wterm * 2560 + wrow * ASTR + wq * 16;

    uint4 pa[4], pw;
    #pragma unroll
    for (int it = 0; it < 4; it++) pa[it] = __ldcg((const uint4*)aptr[it]);
    pw = __ldg((const uint4*)wptr);

    const int nch = K / 32;
    for (int c = 0; c < nch; c++) {
        __syncthreads();   // prior chunk's ldsm (or prior smem user) done
        #pragma unroll
        for (int it = 0; it < 4; it++) *(uint4*)(SM + asoff[it]) = pa[it];
        *(uint4*)(SM + wsoff) = pw;
        if (c + 1 < nch) {
            const int off = (c + 1) * 32;
            #pragma unroll
            for (int it = 0; it < 4; it++)
                pa[it] = __ldcg((const uint4*)(aptr[it] + off));
            pw = __ldg((const uint4*)(wptr + off));
        }
        __syncthreads();
        #pragma unroll
        for (int ks = 0; ks < 32; ks += 16) {
            uint32_t a[2][2][4], w[2][4];
            #pragma unroll
            for (int h = 0; h < 2; h++)
                #pragma unroll
                for (int tt = 0; tt < 2; tt++)
                    ldsm4(a[h][tt], aB + tt * 10240 + h * 16 * ASTR + ks * 2);
            #pragma unroll
            for (int tt = 0; tt < 2; tt++)
                ldsm4(w[tt], wB + tt * 2560 + ks * 2);
            const int PA[4] = {0, 0, 1, 1};
            const int PW[4] = {0, 1, 0, 1};
            #pragma unroll
            for (int p = 0; p < 4; p++)
                #pragma unroll
                for (int h = 0; h < 2; h++)
                    #pragma unroll
                    for (int f = 0; f < 2; f++)
                        mma_bf16(acc[h][f], a[h][PA[p]], w[PW[p]][2*f], w[PW[p]][2*f+1]);
        }
    }
    __syncthreads();   // protect smem-aliased epilogues from in-flight ldsm
}

__global__ void __launch_bounds__(NTHR, 1) lstm_kernel(
    const float* __restrict__ h_n,   const int* __restrict__ expanded,
    const int* __restrict__ tfmask,  const float* __restrict__ dropm,
    const float* __restrict__ embW,
    const float* __restrict__ Wih1,  const float* __restrict__ Whh1,
    const float* __restrict__ bih1,  const float* __restrict__ bhh1,
    const float* __restrict__ Wih2,  const float* __restrict__ Whh2,
    const float* __restrict__ bih2,  const float* __restrict__ bhh2,
    const float* __restrict__ Wout,  const float* __restrict__ bout,
    float* __restrict__ out)
{
    __shared__ __align__(1024) char SM[SMSZ];
    const int tid = threadIdx.x;
    const int blk = blockIdx.x;
    const int j0  = blk * 8;
    const int lane = tid & 31, wid = tid >> 5;
    const int rg = wid >> 1, cgp = wid & 1;
    const int gid = lane >> 2, tig = lane & 3;
    const uint32_t smb = smem_u32(SM);

    // ---------------- init: zero states, x0, pre-convert everything ----------
    for (int i = blk * NTHR + tid; i < 2 * BATCH * HID; i += NBLK * NTHR) {
        int term = i / (BATCH * HID), o = i % (BATCH * HID);
        gbH1[0][term][o] = 0; gbH2[0][term][o] = 0;
    }
    for (int i = blk * NTHR + tid; i < BATCH * EMB; i += NBLK * NTHR) {
        int b = i / EMB; int e = i - b * EMB;
        int tok = expanded[b * SEQT];
        float x = dropm[tok] * embW[(size_t)tok * EMB + e];
        ush a, bb; cvt2(x, a, bb);
        gbX[0][i] = a; gbX[1][i] = bb;
    }
    if (blk == 0)
        for (int i = tid; i < STEPS; i += NTHR) g_ctrC[i] = 0;

    conv_arr(gbW1[0],  gbW1[1],  Wih1, 4096 * LDW1 / 8);
    conv_arr(gbWh1[0], gbWh1[1], Whh1, 4096 * HID / 8);
    conv_arr(gbW2[0],  gbW2[1],  Wih2, 4096 * HID / 8);
    conv_arr(gbWh2[0], gbWh2[1], Whh2, 4096 * HID / 8);
    conv_arr(gbWo[0],  gbWo[1],  Wout, VOC * HID / 8);
    conv_arr(gbHn[0],  gbHn[1],  h_n,  BATCH * CTXW / 8);
    gbar();

    // one-time: g_hn = h_n @ Wih1[:, E:].T + bih1 + bhh1 (this block's gate tile)
    {
        float acc[2][2][4];
        #pragma unroll
        for (int h = 0; h < 2; h++)
            #pragma unroll
            for (int f = 0; f < 2; f++)
                #pragma unroll
                for (int q = 0; q < 4; q++) acc[h][f][q] = 0.f;
        run_gemm<true>(acc, gbHn[0], gbHn[1], CTXW,
                       gbW1[0], gbW1[1], LDW1, EMB, j0, 0, CTXW,
                       SM, smb, tid);
        #pragma unroll
        for (int h = 0; h < 2; h++) {
            int rAr = rg * 32 + h * 16 + gid;
            #pragma unroll
            for (int f = 0; f < 2; f++) {
                int tc = cgp * 16 + f * 8 + 2 * tig;
                int col = ((tc >> 3) * HID) + j0 + (tc & 7);
                float b0 = __ldg(bih1 + col) + __ldg(bhh1 + col);
                float b1 = __ldg(bih1 + col + 1) + __ldg(bhh1 + col + 1);
                *(float2*)&g_hn[(size_t)rAr * G4H + col] =
                    make_float2(acc[h][f][0] + b0, acc[h][f][1] + b1);
                *(float2*)&g_hn[(size_t)(rAr + 8) * G4H + col] =
                    make_float2(acc[h][f][2] + b0, acc[h][f][3] + b1);
            }
        }
    }
    gbar();

    float c1s[4] = {0.f, 0.f, 0.f, 0.f};
    float c2s[4] = {0.f, 0.f, 0.f, 0.f};
    float* sGf = (float*)SM;   // aliased gate tile [128][34]

    for (int t = 0; t < STEPS; t++) {
        const int ob_ = t & 1, nb_ = (t + 1) & 1;

        // ---------- phase A: layer-1 gates + cell ----------
        {
            float acc[2][2][4];
            #pragma unroll
            for (int h = 0; h < 2; h++) {
                int rAr = rg * 32 + h * 16 + gid;
                #pragma unroll
                for (int f = 0; f < 2; f++) {
                    int tc = cgp * 16 + f * 8 + 2 * tig;
                    int col = ((tc >> 3) * HID) + j0 + (tc & 7);
                    float2 u = *(const float2*)&g_hn[(size_t)rAr * G4H + col];
                    float2 v = *(const float2*)&g_hn[(size_t)(rAr + 8) * G4H + col];
                    acc[h][f][0] = u.x; acc[h][f][1] = u.y;
                    acc[h][f][2] = v.x; acc[h][f][3] = v.y;
                }
            }
            run_gemm<true>(acc, gbX[0], gbX[1], EMB,
                           gbW1[0], gbW1[1], LDW1, 0, j0, 0, EMB,
                           SM, smb, tid);
            run_gemm<true>(acc, gbH1[ob_][0], gbH1[ob_][1], HID,
                           gbWh1[0], gbWh1[1], HID, 0, j0, 0, HID,
                           SM, smb, tid);
            #pragma unroll
            for (int h = 0; h < 2; h++) {
                int rAr = rg * 32 + h * 16 + gid;
                #pragma unroll
                for (int f = 0; f < 2; f++) {
                    int tc = cgp * 16 + f * 8 + 2 * tig;
                    *(float2*)&sGf[rAr * 34 + tc] = make_float2(acc[h][f][0], acc[h][f][1]);
                    *(float2*)&sGf[(rAr + 8) * 34 + tc] = make_float2(acc[h][f][2], acc[h][f][3]);
                }
            }
            __syncthreads();
            #pragma unroll
            for (int jj = 0; jj < 4; jj++) {
                int p = tid + jj * NTHR;
                int r = p >> 3, jl = p & 7;
                float iv = sGf[r * 34 + jl];
                float fv = sGf[r * 34 + 8 + jl];
                float gv = sGf[r * 34 + 16 + jl];
                float ov = sGf[r * 34 + 24 + jl];
                float cn = sigmf(fv) * c1s[jj] + sigmf(iv) * tanhf(gv);
                c1s[jj] = cn;
                float hv = sigmf(ov) * tanhf(cn);
                ush a, bb; cvt2(hv, a, bb);
                int o = r * HID + j0 + jl;
                gbH1[nb_][0][o] = a; gbH1[nb_][1][o] = bb;
            }
        }
        gbar();

        // ---------- phase B: layer-2 gates + cell ----------
        {
            float acc[2][2][4];
            #pragma unroll
            for (int f = 0; f < 2; f++) {
                int tc = cgp * 16 + f * 8 + 2 * tig;
                int col = ((tc >> 3) * HID) + j0 + (tc & 7);
                float b0 = __ldg(bih2 + col) + __ldg(bhh2 + col);
                float b1 = __ldg(bih2 + col + 1) + __ldg(bhh2 + col + 1);
                #pragma unroll
                for (int h = 0; h < 2; h++) {
                    acc[h][f][0] = b0; acc[h][f][1] = b1;
                    acc[h][f][2] = b0; acc[h][f][3] = b1;
                }
            }
            run_gemm<true>(acc, gbH1[nb_][0], gbH1[nb_][1], HID,
                           gbW2[0], gbW2[1], HID, 0, j0, 0, HID,
                           SM, smb, tid);
            run_gemm<true>(acc, gbH2[ob_][0], gbH2[ob_][1], HID,
                           gbWh2[0], gbWh2[1], HID, 0, j0, 0, HID,
                           SM, smb, tid);
            #pragma unroll
            for (int h = 0; h < 2; h++) {
                int rAr = rg * 32 + h * 16 + gid;
                #pragma unroll
                for (int f = 0; f < 2; f++) {
                    int tc = cgp * 16 + f * 8 + 2 * tig;
                    *(float2*)&sGf[rAr * 34 + tc] = make_float2(acc[h][f][0], acc[h][f][1]);
                    *(float2*)&sGf[(rAr + 8) * 34 + tc] = make_float2(acc[h][f][2], acc[h][f][3]);
                }
            }
            __syncthreads();
            #pragma unroll
            for (int jj = 0; jj < 4; jj++) {
                int p = tid + jj * NTHR;
                int r = p >> 3, jl = p & 7;
                float iv = sGf[r * 34 + jl];
                float fv = sGf[r * 34 + 8 + jl];
                float gv = sGf[r * 34 + 16 + jl];
                float ov = sGf[r * 34 + 24 + jl];
                float cn = sigmf(fv) * c2s[jj] + sigmf(iv) * tanhf(gv);
                c2s[jj] = cn;
                float hv = sigmf(ov) * tanhf(cn);
                ush a, bb; cvt2(hv, a, bb);
                int o = r * HID + j0 + jl;
                gbH2[nb_][0][o] = a; gbH2[nb_][1][o] = bb;
            }
        }
        gbar();

        // ---------- phase C: logits tiles (work stealing) ----------
        for (;;) {
            __syncthreads();
            if (tid == 0) *(int*)(SM + OTILE) = atomicAdd(&g_ctrC[t], 1);
            __syncthreads();
            int tile = *(int*)(SM + OTILE);
            if (tile >= NTILE) break;
            int n0 = tile * 32;
            float acc[2][2][4];
            #pragma unroll
            for (int h = 0; h < 2; h++)
                #pragma unroll
                for (int f = 0; f < 2; f++)
                    #pragma unroll
                    for (int q = 0; q < 4; q++) acc[h][f][q] = 0.f;
            run_gemm<false>(acc, gbH2[nb_][0], gbH2[nb_][1], HID,
                            gbWo[0], gbWo[1], HID, 0, n0, VOC - 1, HID,
                            SM, smb, tid);
            float* sMxV = (float*)SM;
            int*   sMxI = (int*)(SM + 1024);
            #pragma unroll
            for (int h = 0; h < 2; h++) {
                int rAr = rg * 32 + h * 16 + gid;
                float bvA = -FLT_MAX, bvB = -FLT_MAX;
                int   bcA = 0x7fffffff, bcB = 0x7fffffff;
                #pragma unroll
                for (int f = 0; f < 2; f++) {
                    int col0 = n0 + cgp * 16 + f * 8 + 2 * tig;
                    if (col0 < VOC) {
                        float b0 = __ldg(bout + col0);
                        float b1 = __ldg(bout + col0 + 1);
                        float vA0 = acc[h][f][0] + b0, vA1 = acc[h][f][1] + b1;
                        float vB0 = acc[h][f][2] + b0, vB1 = acc[h][f][3] + b1;
                        *(float2*)&out[((size_t)t * BATCH + rAr) * VOC + col0] =
                            make_float2(vA0, vA1);
                        *(float2*)&out[((size_t)t * BATCH + rAr + 8) * VOC + col0] =
                            make_float2(vB0, vB1);
                        if (vA0 > bvA) { bvA = vA0; bcA = col0; }
                        if (vA1 > bvA) { bvA = vA1; bcA = col0 + 1; }
                        if (vB0 > bvB) { bvB = vB0; bcB = col0; }
                        if (vB1 > bvB) { bvB = vB1; bcB = col0 + 1; }
                    }
                }
                #pragma unroll
                for (int d = 1; d <= 2; d <<= 1) {
                    float ov = __shfl_xor_sync(0xffffffffu, bvA, d);
                    int   oc = __shfl_xor_sync(0xffffffffu, bcA, d);
                    if (ov > bvA || (ov == bvA && oc < bcA)) { bvA = ov; bcA = oc; }
                    ov = __shfl_xor_sync(0xffffffffu, bvB, d);
                    oc = __shfl_xor_sync(0xffffffffu, bcB, d);
                    if (ov > bvB || (ov == bvB && oc < bcB)) { bvB = ov; bcB = oc; }
                }
                if (tig == 0) {
                    sMxV[rAr * 2 + cgp] = bvA; sMxI[rAr * 2 + cgp] = bcA;
                    sMxV[(rAr + 8) * 2 + cgp] = bvB; sMxI[(rAr + 8) * 2 + cgp] = bcB;
                }
            }
            __syncthreads();
            if (tid < BATCH) {
                float v0 = sMxV[tid * 2], v1 = sMxV[tid * 2 + 1];
                int   i0 = sMxI[tid * 2], i1 = sMxI[tid * 2 + 1];
                if (v1 > v0 || (v1 == v0 && i1 < i0)) { v0 = v1; i0 = i1; }
                g_pmax[tid][tile] = v0;
                g_pidx[tid][tile] = i0;
            }
        }
        gbar();

        // ---------- phase D: final argmax + next input ----------
        {
            float* s_rv = (float*)(SM + ORV);
            int*   s_ri = (int*)(SM + ORI);
            int b = blk;
            float bv = -FLT_MAX; int bc = 0x7fffffff;
            for (int tile = tid; tile < NTILE; tile += NTHR) {
                float v = __ldcg(&g_pmax[b][tile]);
                int   c = __ldcg(&g_pidx[b][tile]);
                if (v > bv || (v == bv && c < bc)) { bv = v; bc = c; }
            }
            s_rv[tid] = bv; s_ri[tid] = bc;
            __syncthreads();
            for (int s = NTHR / 2; s > 0; s >>= 1) {
                if (tid < s) {
                    float v = s_rv[tid + s]; int c = s_ri[tid + s];
                    if (v > s_rv[tid] || (v == s_rv[tid] && c < s_ri[tid])) {
                        s_rv[tid] = v; s_ri[tid] = c;
                    }
                }
                __syncthreads();
            }
            if (tid == 0) {
                int m = tfmask[t * BATCH + b];
                int tok; float sc;
                if (m == 1) { tok = s_ri[0]; sc = 1.0f; }
                else        { tok = expanded[b * SEQT + t + 1]; sc = dropm[tok]; }
                *(int*)(SM + OTOK) = tok;
                *(float*)(SM + OSC) = sc;
            }
            __syncthreads();
            int tok = *(int*)(SM + OTOK);
            float sc = *(float*)(SM + OSC);
            #pragma unroll
            for (int e0 = 0; e0 < 2; e0++) {
                int e = tid + e0 * 256;
                float x = sc * embW[(size_t)tok * EMB + e];
                ush a, bb; cvt2(x, a, bb);
                int o = b * EMB + e;
                gbX[0][o] = a; gbX[1][o] = bb;
            }
        }
        gbar();
    }
}

extern "C" void kernel_launch(void* const* d_in, const int* in_sizes, int n_in,
                              void* d_out, int out_size) {
    (void)in_sizes; (void)n_in; (void)out_size;
    lstm_kernel<<<NBLK, NTHR>>>(
        (const float*)d_in[0],  (const int*)d_in[1],  (const int*)d_in[2],
        (const float*)d_in[3],  (const float*)d_in[4], (const float*)d_in[5],
        (const float*)d_in[6],  (const float*)d_in[7], (const float*)d_in[8],
        (const float*)d_in[9],  (const float*)d_in[10], (const float*)d_in[11],
        (const float*)d_in[12], (const float*)d_in[13], (const float*)d_in[14],
        (float*)d_out);
}

// round 17
// speedup vs baseline: 2.2208x; 1.1340x over previous
#include <cuda_runtime.h>
#include <cstdint>
#include <cfloat>
#include <math.h>

#define VOC   10000
#define EMB   512
#define HID   1024
#define BATCH 128
#define SEQT  64
#define STEPS 63
#define CTXW  4096
#define G4H   4096
#define NBLK  128
#define NTHR  256
#define NTILE 313
#define LDW1  (EMB + CTXW)   // 4608

// ---- static smem: DOUBLE-BUFFERED swizzled tiles, 64 B rows (no pad) ----
#define ATERM 8192            // 128 rows * 64 B
#define WOFF  16384           // W region within one buffer
#define WTERM 2048            // 32 rows * 64 B
#define BUFSZ 20480           // 2*ATERM + 2*WTERM
#define OTILE 40960
#define OTOK  40964
#define OSC   40968
#define ORV   41088           // float[256]
#define ORI   42112           // int[256]
#define SMSZ  43136

typedef unsigned short ush;

// swizzled byte offset: row (64B rows), qb = 16B-aligned byte col offset
__device__ __forceinline__ int swz(int row, int qb) {
    return row * 64 + (qb ^ (((row >> 1) & 3) << 4));
}

// ---------------- persistent device scratch ----------------------------------
__device__ __align__(128) float g_hn[BATCH * G4H];
__device__ __align__(128) float g_pmax[BATCH][NTILE];
__device__ __align__(128) int   g_pidx[BATCH][NTILE];
__device__ int g_ctrC[STEPS];
__device__ unsigned g_count;
__device__ unsigned g_gen;

// pre-converted bf16 2-term storage (term 0=hi, 1=mid)
__device__ __align__(128) ush gbW1 [2][4096 * LDW1];
__device__ __align__(128) ush gbWh1[2][4096 * HID];
__device__ __align__(128) ush gbW2 [2][4096 * HID];
__device__ __align__(128) ush gbWh2[2][4096 * HID];
__device__ __align__(128) ush gbWo [2][VOC * HID];
__device__ __align__(128) ush gbHn [2][BATCH * CTXW];
__device__ __align__(128) ush gbX  [2][BATCH * EMB];
__device__ __align__(128) ush gbH1 [2][2][BATCH * HID];
__device__ __align__(128) ush gbH2 [2][2][BATCH * HID];

__device__ __forceinline__ float sigmf(float x) { return 1.0f / (1.0f + expf(-x)); }

__device__ __forceinline__ uint32_t smem_u32(const void* p) {
    uint32_t a;
    asm("{ .reg .u64 t; cvta.to.shared.u64 t, %1; cvt.u32.u64 %0, t; }" : "=r"(a) : "l"(p));
    return a;
}

__device__ __forceinline__ void cvt2(float x, ush& a, ush& b) {
    float f;
    asm("cvt.rn.bf16.f32 %0, %1;" : "=h"(a) : "f"(x));
    asm("cvt.f32.bf16 %0, %1;" : "=f"(f) : "h"(a));
    asm("cvt.rn.bf16.f32 %0, %1;" : "=h"(b) : "f"(x - f));
}

// grid-strided fp32 -> 2xbf16 conversion, 8 elems per iteration
__device__ void conv_arr(ush* d0, ush* d1, const float* __restrict__ s, int n8) {
    const int stride = NBLK * NTHR;
    for (int i = blockIdx.x * NTHR + threadIdx.x; i < n8; i += stride) {
        const float4* p = (const float4*)(s + (size_t)i * 8);
        float4 v0 = __ldcg(p), v1 = __ldcg(p + 1);
        float xs[8] = {v0.x, v0.y, v0.z, v0.w, v1.x, v1.y, v1.z, v1.w};
        ush t0[8], t1[8];
        #pragma unroll
        for (int e = 0; e < 8; e++) cvt2(xs[e], t0[e], t1[e]);
        uint4 u;
        u.x = t0[0] | ((uint32_t)t0[1] << 16); u.y = t0[2] | ((uint32_t)t0[3] << 16);
        u.z = t0[4] | ((uint32_t)t0[5] << 16); u.w = t0[6] | ((uint32_t)t0[7] << 16);
        *(uint4*)(d0 + (size_t)i * 8) = u;
        u.x = t1[0] | ((uint32_t)t1[1] << 16); u.y = t1[2] | ((uint32_t)t1[3] << 16);
        u.z = t1[4] | ((uint32_t)t1[5] << 16); u.w = t1[6] | ((uint32_t)t1[7] << 16);
        *(uint4*)(d1 + (size_t)i * 8) = u;
    }
}

// ---------------- grid-wide sense barrier ------------------------------------
__device__ __forceinline__ void gbar() {
    __syncthreads();
    if (threadIdx.x == 0) {
        __threadfence();
        unsigned gen = *((volatile unsigned*)&g_gen);
        unsigned arrived = atomicAdd(&g_count, 1);
        if (arrived == NBLK - 1) {
            atomicExch(&g_count, 0);
            __threadfence();
            atomicAdd(&g_gen, 1);
        } else {
            while (*((volatile unsigned*)&g_gen) == gen) __nanosleep(64);
        }
        __threadfence();
    }
    __syncthreads();
}

// ---------------- warp-MMA primitives (base sm_80 PTX) ------------------------
__device__ __forceinline__ void ldsm4(uint32_t (&r)[4], uint32_t addr) {
    asm volatile("ldmatrix.sync.aligned.m8n8.x4.shared.b16 {%0,%1,%2,%3}, [%4];"
        : "=r"(r[0]), "=r"(r[1]), "=r"(r[2]), "=r"(r[3]) : "r"(addr));
}
__device__ __forceinline__ void mma_bf16(float (&c)[4], const uint32_t (&a)[4],
                                         uint32_t b0, uint32_t b1) {
    asm volatile("mma.sync.aligned.m16n8k16.row.col.f32.bf16.bf16.f32 "
        "{%0,%1,%2,%3}, {%4,%5,%6,%7}, {%8,%9}, {%0,%1,%2,%3};"
        : "+f"(c[0]), "+f"(c[1]), "+f"(c[2]), "+f"(c[3])
        : "r"(a[0]), "r"(a[1]), "r"(a[2]), "r"(a[3]), "r"(b0), "r"(b1));
}

// ---------------- GEMM: C[128x32] += A[128xK] * Wsel^T ------------------------
// 2-term bf16 split, 4 mma passes per k16 slice, 2 slices per K=32 chunk.
// DOUBLE-BUFFERED swizzled smem: ONE __syncthreads per chunk; STS of chunk c+1
// (other buffer) overlaps the MMA tail of chunk c. LDG register-prefetched.
template<bool GATED>
__device__ __forceinline__ void run_gemm(float (&acc)[2][2][4],
    const ush* __restrict__ A0, const ush* __restrict__ A1, int lda,
    const ush* __restrict__ W0, const ush* __restrict__ W1, int ldw, int wcol0,
    int rowsel, int rowclamp, int K,
    char* SM, uint32_t smb, int tid)
{
    const int lane = tid & 31, wid = tid >> 5;
    const int rg = wid >> 1, cgp = wid & 1;
    const int sub = lane >> 3, rin = lane & 7;
    const int rA = rg * 32 + ((sub & 1) << 3) + rin;
    const int cA = (sub >> 1) << 3;                   // 0 or 8 cols -> 0/16 B
    const int rW = cgp * 16 + ((sub >> 1) << 3) + rin;
    const int cW = (sub & 1) << 3;

    // A staging: 4 slots/thread -> 2 terms x 128 rows x 4 uint4
    const ush* aptr[4]; int asoff[4];
    #pragma unroll
    for (int it = 0; it < 4; it++) {
        int idx = tid + it * 256;
        int term = idx >> 9, rem = idx & 511;
        int row = rem >> 2, q = rem & 3;
        const ush* Ap = term ? A1 : A0;
        aptr[it] = Ap + (size_t)row * lda + q * 8;
        asoff[it] = term * ATERM + swz(row, q * 16);
    }
    // W staging: 1 slot/thread: term=tid>>7, row=(tid&127)>>2, quad=tid&3
    const int wterm = tid >> 7;
    const int wrow = (tid & 127) >> 2, wq = tid & 3;
    int grow;
    if (GATED) grow = (wrow >> 3) * HID + rowsel + (wrow & 7);
    else { grow = rowsel + wrow; if (grow > rowclamp) grow = rowclamp; }
    const ush* Wp = wterm ? W1 : W0;
    const ush* wptr = Wp + (size_t)grow * ldw + wcol0 + wq * 8;
    const int wsoff = WOFF + wterm * WTERM + swz(wrow, wq * 16);

    uint4 pa[4], pw;
    #pragma unroll
    for (int it = 0; it < 4; it++) pa[it] = __ldcg((const uint4*)aptr[it]);
    pw = __ldg((const uint4*)wptr);

    const int nch = K / 32;
    __syncthreads();   // prior smem users (epilogue / previous gemm) done
    for (int c = 0; c < nch; c++) {
        const int bo = (c & 1) * BUFSZ;
        #pragma unroll
        for (int it = 0; it < 4; it++) *(uint4*)(SM + bo + asoff[it]) = pa[it];
        *(uint4*)(SM + bo + wsoff) = pw;
        if (c + 1 < nch) {
            const int off = (c + 1) * 32;
            #pragma unroll
            for (int it = 0; it < 4; it++)
                pa[it] = __ldcg((const uint4*)(aptr[it] + off));
            pw = __ldg((const uint4*)(wptr + off));
        }
        __syncthreads();
        #pragma unroll
        for (int ks = 0; ks < 32; ks += 16) {
            uint32_t a[2][2][4], w[2][4];
            #pragma unroll
            for (int h = 0; h < 2; h++)
                #pragma unroll
                for (int tt = 0; tt < 2; tt++)
                    ldsm4(a[h][tt], smb + bo + tt * ATERM +
                                    swz(rA + h * 16, cA * 2 + ks * 2));
            #pragma unroll
            for (int tt = 0; tt < 2; tt++)
                ldsm4(w[tt], smb + bo + WOFF + tt * WTERM +
                             swz(rW, cW * 2 + ks * 2));
            const int PA[4] = {0, 0, 1, 1};
            const int PW[4] = {0, 1, 0, 1};
            #pragma unroll
            for (int p = 0; p < 4; p++)
                #pragma unroll
                for (int h = 0; h < 2; h++)
                    #pragma unroll
                    for (int f = 0; f < 2; f++)
                        mma_bf16(acc[h][f], a[h][PA[p]], w[PW[p]][2*f], w[PW[p]][2*f+1]);
        }
    }
    __syncthreads();   // protect smem-aliased epilogues from in-flight ldsm
}

__global__ void __launch_bounds__(NTHR, 1) lstm_kernel(
    const float* __restrict__ h_n,   const int* __restrict__ expanded,
    const int* __restrict__ tfmask,  const float* __restrict__ dropm,
    const float* __restrict__ embW,
    const float* __restrict__ Wih1,  const float* __restrict__ Whh1,
    const float* __restrict__ bih1,  const float* __restrict__ bhh1,
    const float* __restrict__ Wih2,  const float* __restrict__ Whh2,
    const float* __restrict__ bih2,  const float* __restrict__ bhh2,
    const float* __restrict__ Wout,  const float* __restrict__ bout,
    float* __restrict__ out)
{
    __shared__ __align__(1024) char SM[SMSZ];
    const int tid = threadIdx.x;
    const int blk = blockIdx.x;
    const int j0  = blk * 8;
    const int lane = tid & 31, wid = tid >> 5;
    const int rg = wid >> 1, cgp = wid & 1;
    const int gid = lane >> 2, tig = lane & 3;
    const uint32_t smb = smem_u32(SM);

    // ---------------- init: zero states, x0, pre-convert everything ----------
    for (int i = blk * NTHR + tid; i < 2 * BATCH * HID; i += NBLK * NTHR) {
        int term = i / (BATCH * HID), o = i % (BATCH * HID);
        gbH1[0][term][o] = 0; gbH2[0][term][o] = 0;
    }
    for (int i = blk * NTHR + tid; i < BATCH * EMB; i += NBLK * NTHR) {
        int b = i / EMB; int e = i - b * EMB;
        int tok = expanded[b * SEQT];
        float x = dropm[tok] * embW[(size_t)tok * EMB + e];
        ush a, bb; cvt2(x, a, bb);
        gbX[0][i] = a; gbX[1][i] = bb;
    }
    if (blk == 0)
        for (int i = tid; i < STEPS; i += NTHR) g_ctrC[i] = 0;

    conv_arr(gbW1[0],  gbW1[1],  Wih1, 4096 * LDW1 / 8);
    conv_arr(gbWh1[0], gbWh1[1], Whh1, 4096 * HID / 8);
    conv_arr(gbW2[0],  gbW2[1],  Wih2, 4096 * HID / 8);
    conv_arr(gbWh2[0], gbWh2[1], Whh2, 4096 * HID / 8);
    conv_arr(gbWo[0],  gbWo[1],  Wout, VOC * HID / 8);
    conv_arr(gbHn[0],  gbHn[1],  h_n,  BATCH * CTXW / 8);
    gbar();

    // one-time: g_hn = h_n @ Wih1[:, E:].T + bih1 + bhh1 (this block's gate tile)
    {
        float acc[2][2][4];
        #pragma unroll
        for (int h = 0; h < 2; h++)
            #pragma unroll
            for (int f = 0; f < 2; f++)
                #pragma unroll
                for (int q = 0; q < 4; q++) acc[h][f][q] = 0.f;
        run_gemm<true>(acc, gbHn[0], gbHn[1], CTXW,
                       gbW1[0], gbW1[1], LDW1, EMB, j0, 0, CTXW,
                       SM, smb, tid);
        #pragma unroll
        for (int h = 0; h < 2; h++) {
            int rAr = rg * 32 + h * 16 + gid;
            #pragma unroll
            for (int f = 0; f < 2; f++) {
                int tc = cgp * 16 + f * 8 + 2 * tig;
                int col = ((tc >> 3) * HID) + j0 + (tc & 7);
                float b0 = __ldg(bih1 + col) + __ldg(bhh1 + col);
                float b1 = __ldg(bih1 + col + 1) + __ldg(bhh1 + col + 1);
                *(float2*)&g_hn[(size_t)rAr * G4H + col] =
                    make_float2(acc[h][f][0] + b0, acc[h][f][1] + b1);
                *(float2*)&g_hn[(size_t)(rAr + 8) * G4H + col] =
                    make_float2(acc[h][f][2] + b0, acc[h][f][3] + b1);
            }
        }
    }
    gbar();

    float c1s[4] = {0.f, 0.f, 0.f, 0.f};
    float c2s[4] = {0.f, 0.f, 0.f, 0.f};
    float* sGf = (float*)SM;   // aliased gate tile [128][34]

    for (int t = 0; t < STEPS; t++) {
        const int ob_ = t & 1, nb_ = (t + 1) & 1;

        // ---------- phase A: layer-1 gates + cell ----------
        {
            float acc[2][2][4];
            #pragma unroll
            for (int h = 0; h < 2; h++) {
                int rAr = rg * 32 + h * 16 + gid;
                #pragma unroll
                for (int f = 0; f < 2; f++) {
                    int tc = cgp * 16 + f * 8 + 2 * tig;
                    int col = ((tc >> 3) * HID) + j0 + (tc & 7);
                    float2 u = *(const float2*)&g_hn[(size_t)rAr * G4H + col];
                    float2 v = *(const float2*)&g_hn[(size_t)(rAr + 8) * G4H + col];
                    acc[h][f][0] = u.x; acc[h][f][1] = u.y;
                    acc[h][f][2] = v.x; acc[h][f][3] = v.y;
                }
            }
            run_gemm<true>(acc, gbX[0], gbX[1], EMB,
                           gbW1[0], gbW1[1], LDW1, 0, j0, 0, EMB,
                           SM, smb, tid);
            run_gemm<true>(acc, gbH1[ob_][0], gbH1[ob_][1], HID,
                           gbWh1[0], gbWh1[1], HID, 0, j0, 0, HID,
                           SM, smb, tid);
            #pragma unroll
            for (int h = 0; h < 2; h++) {
                int rAr = rg * 32 + h * 16 + gid;
                #pragma unroll
                for (int f = 0; f < 2; f++) {
                    int tc = cgp * 16 + f * 8 + 2 * tig;
                    *(float2*)&sGf[rAr * 34 + tc] = make_float2(acc[h][f][0], acc[h][f][1]);
                    *(float2*)&sGf[(rAr + 8) * 34 + tc] = make_float2(acc[h][f][2], acc[h][f][3]);
                }
            }
            __syncthreads();
            #pragma unroll
            for (int jj = 0; jj < 4; jj++) {
                int p = tid + jj * NTHR;
                int r = p >> 3, jl = p & 7;
                float iv = sGf[r * 34 + jl];
                float fv = sGf[r * 34 + 8 + jl];
                float gv = sGf[r * 34 + 16 + jl];
                float ov = sGf[r * 34 + 24 + jl];
                float cn = sigmf(fv) * c1s[jj] + sigmf(iv) * tanhf(gv);
                c1s[jj] = cn;
                float hv = sigmf(ov) * tanhf(cn);
                ush a, bb; cvt2(hv, a, bb);
                int o = r * HID + j0 + jl;
                gbH1[nb_][0][o] = a; gbH1[nb_][1][o] = bb;
            }
        }
        gbar();

        // ---------- phase B: layer-2 gates + cell ----------
        {
            float acc[2][2][4];
            #pragma unroll
            for (int f = 0; f < 2; f++) {
                int tc = cgp * 16 + f * 8 + 2 * tig;
                int col = ((tc >> 3) * HID) + j0 + (tc & 7);
                float b0 = __ldg(bih2 + col) + __ldg(bhh2 + col);
                float b1 = __ldg(bih2 + col + 1) + __ldg(bhh2 + col + 1);
                #pragma unroll
                for (int h = 0; h < 2; h++) {
                    acc[h][f][0] = b0; acc[h][f][1] = b1;
                    acc[h][f][2] = b0; acc[h][f][3] = b1;
                }
            }
            run_gemm<true>(acc, gbH1[nb_][0], gbH1[nb_][1], HID,
                           gbW2[0], gbW2[1], HID, 0, j0, 0, HID,
                           SM, smb, tid);
            run_gemm<true>(acc, gbH2[ob_][0], gbH2[ob_][1], HID,
                           gbWh2[0], gbWh2[1], HID, 0, j0, 0, HID,
                           SM, smb, tid);
            #pragma unroll
            for (int h = 0; h < 2; h++) {
                int rAr = rg * 32 + h * 16 + gid;
                #pragma unroll
                for (int f = 0; f < 2; f++) {
                    int tc = cgp * 16 + f * 8 + 2 * tig;
                    *(float2*)&sGf[rAr * 34 + tc] = make_float2(acc[h][f][0], acc[h][f][1]);
                    *(float2*)&sGf[(rAr + 8) * 34 + tc] = make_float2(acc[h][f][2], acc[h][f][3]);
                }
            }
            __syncthreads();
            #pragma unroll
            for (int jj = 0; jj < 4; jj++) {
                int p = tid + jj * NTHR;
                int r = p >> 3, jl = p & 7;
                float iv = sGf[r * 34 + jl];
                float fv = sGf[r * 34 + 8 + jl];
                float gv = sGf[r * 34 + 16 + jl];
                float ov = sGf[r * 34 + 24 + jl];
                float cn = sigmf(fv) * c2s[jj] + sigmf(iv) * tanhf(gv);
                c2s[jj] = cn;
                float hv = sigmf(ov) * tanhf(cn);
                ush a, bb; cvt2(hv, a, bb);
                int o = r * HID + j0 + jl;
                gbH2[nb_][0][o] = a; gbH2[nb_][1][o] = bb;
            }
        }
        gbar();

        // ---------- phase C: logits tiles (work stealing) ----------
        for (;;) {
            __syncthreads();
            if (tid == 0) *(int*)(SM + OTILE) = atomicAdd(&g_ctrC[t], 1);
            __syncthreads();
            int tile = *(int*)(SM + OTILE);
            if (tile >= NTILE) break;
            int n0 = tile * 32;
            float acc[2][2][4];
            #pragma unroll
            for (int h = 0; h < 2; h++)
                #pragma unroll
                for (int f = 0; f < 2; f++)
                    #pragma unroll
                    for (int q = 0; q < 4; q++) acc[h][f][q] = 0.f;
            run_gemm<false>(acc, gbH2[nb_][0], gbH2[nb_][1], HID,
                            gbWo[0], gbWo[1], HID, 0, n0, VOC - 1, HID,
                            SM, smb, tid);
            float* sMxV = (float*)SM;
            int*   sMxI = (int*)(SM + 1024);
            #pragma unroll
            for (int h = 0; h < 2; h++) {
                int rAr = rg * 32 + h * 16 + gid;
                float bvA = -FLT_MAX, bvB = -FLT_MAX;
                int   bcA = 0x7fffffff, bcB = 0x7fffffff;
                #pragma unroll
                for (int f = 0; f < 2; f++) {
                    int col0 = n0 + cgp * 16 + f * 8 + 2 * tig;
                    if (col0 < VOC) {
                        float b0 = __ldg(bout + col0);
                        float b1 = __ldg(bout + col0 + 1);
                        float vA0 = acc[h][f][0] + b0, vA1 = acc[h][f][1] + b1;
                        float vB0 = acc[h][f][2] + b0, vB1 = acc[h][f][3] + b1;
                        *(float2*)&out[((size_t)t * BATCH + rAr) * VOC + col0] =
                            make_float2(vA0, vA1);
                        *(float2*)&out[((size_t)t * BATCH + rAr + 8) * VOC + col0] =
                            make_float2(vB0, vB1);
                        if (vA0 > bvA) { bvA = vA0; bcA = col0; }
                        if (vA1 > bvA) { bvA = vA1; bcA = col0 + 1; }
                        if (vB0 > bvB) { bvB = vB0; bcB = col0; }
                        if (vB1 > bvB) { bvB = vB1; bcB = col0 + 1; }
                    }
                }
                #pragma unroll
                for (int d = 1; d <= 2; d <<= 1) {
                    float ov = __shfl_xor_sync(0xffffffffu, bvA, d);
                    int   oc = __shfl_xor_sync(0xffffffffu, bcA, d);
                    if (ov > bvA || (ov == bvA && oc < bcA)) { bvA = ov; bcA = oc; }
                    ov = __shfl_xor_sync(0xffffffffu, bvB, d);
                    oc = __shfl_xor_sync(0xffffffffu, bcB, d);
                    if (ov > bvB || (ov == bvB && oc < bcB)) { bvB = ov; bcB = oc; }
                }
                if (tig == 0) {
                    sMxV[rAr * 2 + cgp] = bvA; sMxI[rAr * 2 + cgp] = bcA;
                    sMxV[(rAr + 8) * 2 + cgp] = bvB; sMxI[(rAr + 8) * 2 + cgp] = bcB;
                }
            }
            __syncthreads();
            if (tid < BATCH) {
                float v0 = sMxV[tid * 2], v1 = sMxV[tid * 2 + 1];
                int   i0 = sMxI[tid * 2], i1 = sMxI[tid * 2 + 1];
                if (v1 > v0 || (v1 == v0 && i1 < i0)) { v0 = v1; i0 = i1; }
                g_pmax[tid][tile] = v0;
                g_pidx[tid][tile] = i0;
            }
        }
        gbar();

        // ---------- phase D: final argmax + next input ----------
        {
            float* s_rv = (float*)(SM + ORV);
            int*   s_ri = (int*)(SM + ORI);
            int b = blk;
            float bv = -FLT_MAX; int bc = 0x7fffffff;
            for (int tile = tid; tile < NTILE; tile += NTHR) {
                float v = __ldcg(&g_pmax[b][tile]);
                int   c = __ldcg(&g_pidx[b][tile]);
                if (v > bv || (v == bv && c < bc)) { bv = v; bc = c; }
            }
            s_rv[tid] = bv; s_ri[tid] = bc;
            __syncthreads();
            for (int s = NTHR / 2; s > 0; s >>= 1) {
                if (tid < s) {
                    float v = s_rv[tid + s]; int c = s_ri[tid + s];
                    if (v > s_rv[tid] || (v == s_rv[tid] && c < s_ri[tid])) {
                        s_rv[tid] = v; s_ri[tid] = c;
                    }
                }
                __syncthreads();
            }
            if (tid == 0) {
                int m = tfmask[t * BATCH + b];
                int tok; float sc;
                if (m == 1) { tok = s_ri[0]; sc = 1.0f; }
                else        { tok = expanded[b * SEQT + t + 1]; sc = dropm[tok]; }
                *(int*)(SM + OTOK) = tok;
                *(float*)(SM + OSC) = sc;
            }
            __syncthreads();
            int tok = *(int*)(SM + OTOK);
            float sc = *(float*)(SM + OSC);
            #pragma unroll
            for (int e0 = 0; e0 < 2; e0++) {
                int e = tid + e0 * 256;
                float x = sc * embW[(size_t)tok * EMB + e];
                ush a, bb; cvt2(x, a, bb);
                int o = b * EMB + e;
                gbX[0][o] = a; gbX[1][o] = bb;
            }
        }
        gbar();
    }
}

extern "C" void kernel_launch(void* const* d_in, const int* in_sizes, int n_in,
                              void* d_out, int out_size) {
    (void)in_sizes; (void)n_in; (void)out_size;
    lstm_kernel<<<NBLK, NTHR>>>(
        (const float*)d_in[0],  (const int*)d_in[1],  (const int*)d_in[2],
        (const float*)d_in[3],  (const float*)d_in[4], (const float*)d_in[5],
        (const float*)d_in[6],  (const float*)d_in[7], (const float*)d_in[8],
        (const float*)d_in[9],  (const float*)d_in[10], (const float*)d_in[11],
        (const float*)d_in[12], (const float*)d_in[13], (const float*)d_in[14],
        (float*)d_out);
}